// round 1
// baseline (speedup 1.0000x reference)
#include <cuda_runtime.h>
#include <math.h>

// Problem constants
#define BB 2
#define TT 2048
#define CC 2048
#define HH 16
#define DD 128
#define BH (BB*HH)          // 32

// ---------------- scratch (device globals, no allocation) ----------------
__device__ float g_q[(size_t)BB*HH*TT*DD];       // 8.4M floats
__device__ float g_k[(size_t)BB*HH*TT*DD];
__device__ float g_v[(size_t)BB*HH*TT*DD];
__device__ float g_s[(size_t)BH*TT*TT];          // 134M floats (537MB)
__device__ float g_y[(size_t)BB*TT*CC];          // 8.4M floats

// ---------------- generic tiled SGEMM ----------------
// C = alpha * A * op(B);  A row-major (lda), B row-major (ldb).
// TRANS_B==1: computes A * B^T where B is (N x K) row-major.
// SPLIT==1: epilogue scatters qkv GEMM output into g_q/g_k/g_v [B,H,T,D].
// Batch: z = blockIdx.z;  A += z*batchA; B += z*batchB;
//        C offset = (z/cH)*cOut + (z%cH)*cInn.
template<int TRANS_B, int SPLIT>
__global__ __launch_bounds__(256)
void sgemm(const float* __restrict__ A, const float* __restrict__ B,
           float* __restrict__ C,
           int M, int N, int K, int lda, int ldb, int ldc,
           long batchA, long batchB, long cOut, long cInn, int cH,
           float alpha)
{
    __shared__ float As[16][132];
    __shared__ float Bs[16][132];

    const int tid = threadIdx.x;
    const int tx  = tid & 15;     // 0..15 -> N direction (8 cols each)
    const int ty  = tid >> 4;     // 0..15 -> M direction (8 rows each)

    const int z  = blockIdx.z;
    A += (long)z * batchA;
    B += (long)z * batchB;
    const long coff = (long)(z / cH) * cOut + (long)(z % cH) * cInn;

    const int bn = blockIdx.x * 128;
    const int bm = blockIdx.y * 128;

    float acc[8][8];
    #pragma unroll
    for (int i = 0; i < 8; i++)
        #pragma unroll
        for (int j = 0; j < 8; j++) acc[i][j] = 0.f;

    for (int k0 = 0; k0 < K; k0 += 16) {
        // ---- load A tile (transpose into As[k][m]) ----
        #pragma unroll
        for (int p = 0; p < 2; p++) {
            int i = tid + p * 256;
            int m  = i >> 2;
            int kv = i & 3;
            float4 v = *(const float4*)&A[(long)(bm + m) * lda + k0 + kv * 4];
            As[kv*4+0][m] = v.x;
            As[kv*4+1][m] = v.y;
            As[kv*4+2][m] = v.z;
            As[kv*4+3][m] = v.w;
        }
        // ---- load B tile into Bs[k][n] ----
        if (TRANS_B) {
            #pragma unroll
            for (int p = 0; p < 2; p++) {
                int i = tid + p * 256;
                int n  = i >> 2;
                int kv = i & 3;
                float4 v = *(const float4*)&B[(long)(bn + n) * ldb + k0 + kv * 4];
                Bs[kv*4+0][n] = v.x;
                Bs[kv*4+1][n] = v.y;
                Bs[kv*4+2][n] = v.z;
                Bs[kv*4+3][n] = v.w;
            }
        } else {
            #pragma unroll
            for (int p = 0; p < 2; p++) {
                int i = tid + p * 256;
                int k  = i >> 5;
                int n4 = i & 31;
                float4 v = *(const float4*)&B[(long)(k0 + k) * ldb + bn + n4 * 4];
                *(float4*)&Bs[k][n4 * 4] = v;
            }
        }
        __syncthreads();

        // ---- compute ----
        #pragma unroll
        for (int kk = 0; kk < 16; kk++) {
            float4 a0 = *(const float4*)&As[kk][ty * 8];
            float4 a1 = *(const float4*)&As[kk][ty * 8 + 4];
            float4 b0 = *(const float4*)&Bs[kk][tx * 8];
            float4 b1 = *(const float4*)&Bs[kk][tx * 8 + 4];
            float a[8] = {a0.x,a0.y,a0.z,a0.w,a1.x,a1.y,a1.z,a1.w};
            float b[8] = {b0.x,b0.y,b0.z,b0.w,b1.x,b1.y,b1.z,b1.w};
            #pragma unroll
            for (int i = 0; i < 8; i++)
                #pragma unroll
                for (int j = 0; j < 8; j++)
                    acc[i][j] = fmaf(a[i], b[j], acc[i][j]);
        }
        __syncthreads();
    }

    // ---- epilogue ----
    if (!SPLIT) {
        float* Cb = C + coff;
        #pragma unroll
        for (int i = 0; i < 8; i++) {
            long row = bm + ty * 8 + i;
            float4 o0 = make_float4(alpha*acc[i][0], alpha*acc[i][1],
                                    alpha*acc[i][2], alpha*acc[i][3]);
            float4 o1 = make_float4(alpha*acc[i][4], alpha*acc[i][5],
                                    alpha*acc[i][6], alpha*acc[i][7]);
            *(float4*)&Cb[row * ldc + bn + tx * 8]     = o0;
            *(float4*)&Cb[row * ldc + bn + tx * 8 + 4] = o1;
        }
    } else {
        // qkv epilogue: n in [0,6144); sel = q/k/v, h = head, d = dim.
        int n   = bn + tx * 8;
        int sel = n >> 11;          // /2048
        int rem = n & 2047;
        int h   = rem >> 7;
        int d   = rem & 127;
        float* dst = (sel == 0) ? g_q : (sel == 1) ? g_k : g_v;
        #pragma unroll
        for (int i = 0; i < 8; i++) {
            int m = bm + ty * 8 + i;
            int b = m >> 11;        // /T
            int t = m & 2047;
            long addr = (((long)(b * HH + h) * TT + t) * DD + d);
            float4 o0 = make_float4(acc[i][0], acc[i][1], acc[i][2], acc[i][3]);
            float4 o1 = make_float4(acc[i][4], acc[i][5], acc[i][6], acc[i][7]);
            *(float4*)&dst[addr]     = o0;
            *(float4*)&dst[addr + 4] = o1;
        }
    }
}

// ---------------- RoPE (in place on g_q, g_k) ----------------
// Each thread owns one (b,h,t,d<64) pair and writes both halves.
__global__ __launch_bounds__(256)
void rope_kernel(const float* __restrict__ cosb, const float* __restrict__ sinb)
{
    long idx = (long)blockIdx.x * blockDim.x + threadIdx.x;
    const long total = (long)BB * HH * TT * 64;
    if (idx >= total) return;
    int d = idx & 63;
    long r = idx >> 6;                 // (b*H + h)*T + t
    int t = (int)(r % TT);
    long base = r * DD + d;
    float c = cosb[t * DD + d];        // cos[t][d] == cos[t][d+64]
    float s = sinb[t * DD + d];
    float q0 = g_q[base], q1 = g_q[base + 64];
    g_q[base]      = q0 * c - q1 * s;
    g_q[base + 64] = q1 * c + q0 * s;
    float k0 = g_k[base], k1 = g_k[base + 64];
    g_k[base]      = k0 * c - k1 * s;
    g_k[base + 64] = k1 * c + k0 * s;
}

// ---------------- row softmax over g_s (one pass, regs) ----------------
__global__ __launch_bounds__(256)
void softmax_kernel()
{
    long row = blockIdx.x;                 // B*H*T rows
    float* p = g_s + row * (long)TT;
    int tid = threadIdx.x;
    float v[8];
    float mx = -1e30f;
    #pragma unroll
    for (int i = 0; i < 8; i++) {
        v[i] = p[tid + i * 256];
        mx = fmaxf(mx, v[i]);
    }
    __shared__ float sm[8];
    #pragma unroll
    for (int o = 16; o; o >>= 1) mx = fmaxf(mx, __shfl_xor_sync(0xffffffffu, mx, o));
    if ((tid & 31) == 0) sm[tid >> 5] = mx;
    __syncthreads();
    float rowmax = sm[0];
    #pragma unroll
    for (int w = 1; w < 8; w++) rowmax = fmaxf(rowmax, sm[w]);
    __syncthreads();

    float sum = 0.f;
    #pragma unroll
    for (int i = 0; i < 8; i++) {
        v[i] = expf(v[i] - rowmax);
        sum += v[i];
    }
    #pragma unroll
    for (int o = 16; o; o >>= 1) sum += __shfl_xor_sync(0xffffffffu, sum, o);
    if ((tid & 31) == 0) sm[tid >> 5] = sum;
    __syncthreads();
    float rowsum = 0.f;
    #pragma unroll
    for (int w = 0; w < 8; w++) rowsum += sm[w];
    float inv = 1.f / rowsum;
    #pragma unroll
    for (int i = 0; i < 8; i++) p[tid + i * 256] = v[i] * inv;
}

// ---------------- launch ----------------
extern "C" void kernel_launch(void* const* d_in, const int* in_sizes, int n_in,
                              void* d_out, int out_size)
{
    const float* x     = (const float*)d_in[0];
    const float* cosb  = (const float*)d_in[1];
    const float* sinb  = (const float*)d_in[2];
    const float* Wqkv  = (const float*)d_in[3];
    const float* Wproj = (const float*)d_in[4];
    float* out = (float*)d_out;

    float *q, *k, *v, *s, *y;
    cudaGetSymbolAddress((void**)&q, g_q);
    cudaGetSymbolAddress((void**)&k, g_k);
    cudaGetSymbolAddress((void**)&v, g_v);
    cudaGetSymbolAddress((void**)&s, g_s);
    cudaGetSymbolAddress((void**)&y, g_y);

    const float scale = 0.08838834764831845f;  // 1/sqrt(128)

    // 1) qkv = x @ W_qkv, scattered to g_q/g_k/g_v [B,H,T,D]
    sgemm<0,1><<<dim3(48, 32, 1), 256>>>(
        x, Wqkv, nullptr,
        4096, 6144, 2048, 2048, 6144, 0,
        0L, 0L, 0L, 0L, 1, 1.0f);

    // 2) RoPE in place on q, k
    rope_kernel<<<16384, 256>>>(cosb, sinb);

    // 3) scores = scale * Q @ K^T  (batched over B*H = 32)
    sgemm<1,0><<<dim3(16, 16, BH), 256>>>(
        q, k, s,
        2048, 2048, 128, 128, 128, 2048,
        (long)TT * DD, (long)TT * DD, (long)TT * TT, 0L, 1, scale);

    // 4) softmax rows
    softmax_kernel<<<BH * TT, 256>>>();

    // 5) y = attn @ V, written straight into [B,T,H*D] layout
    sgemm<0,0><<<dim3(1, 16, BH), 256>>>(
        s, v, y,
        2048, 128, 2048, 2048, 128, 2048,
        (long)TT * TT, (long)TT * DD, (long)TT * CC, 128L, HH, 1.0f);

    // 6) out = y @ W_proj
    sgemm<0,0><<<dim3(16, 32, 1), 256>>>(
        y, Wproj, out,
        4096, 2048, 2048, 2048, 2048, 2048,
        0L, 0L, 0L, 0L, 1, 1.0f);
}

// round 2
// speedup vs baseline: 2.2370x; 2.2370x over previous
#include <cuda_runtime.h>
#include <stdint.h>
#include <math.h>

// Problem constants
#define BB 2
#define TT 2048
#define CC 2048
#define HH 16
#define DD 128
#define BH (BB*HH)          // 32

// ---------------- scratch (device globals, no allocation) ----------------
__device__ float g_q[(size_t)BB*HH*TT*DD];
__device__ float g_k[(size_t)BB*HH*TT*DD];
__device__ float g_v[(size_t)BB*HH*TT*DD];
__device__ float g_s[(size_t)BH*TT*TT];
__device__ float g_y[(size_t)BB*TT*CC];

// ---------------- tf32 helpers ----------------
__device__ __forceinline__ uint32_t to_tf32(float x) {
    uint32_t y;
    asm("cvt.rna.tf32.f32 %0, %1;" : "=r"(y) : "f"(x));
    return y;
}

__device__ __forceinline__ void mma_tf32(float* d, const uint32_t* a, const uint32_t* b) {
    asm volatile(
        "mma.sync.aligned.m16n8k8.row.col.f32.tf32.tf32.f32 "
        "{%0,%1,%2,%3}, {%4,%5,%6,%7}, {%8,%9}, {%0,%1,%2,%3};"
        : "+f"(d[0]), "+f"(d[1]), "+f"(d[2]), "+f"(d[3])
        : "r"(a[0]), "r"(a[1]), "r"(a[2]), "r"(a[3]),
          "r"(b[0]), "r"(b[1]));
}

// ---------------- tf32 tensor-core GEMM ----------------
// C = alpha * A * op(B);  A row-major (lda), B row-major (ldb).
// TRANS_B==1: A * B^T with B (N x K) row-major.
// SPLIT==1: epilogue scatters qkv GEMM output into g_q/g_k/g_v [B,H,T,D].
// Batch: z = blockIdx.z;  A += z*batchA; B += z*batchB;
//        C offset = (z/cH)*cOut + (z%cH)*cInn.
// Block tile 128x128, K-tile 16, 8 warps (4 in M x 2 in N), warp tile 32x64.
#define SPAD 136
template<int TRANS_B, int SPLIT>
__global__ __launch_bounds__(256)
void mmagemm(const float* __restrict__ A, const float* __restrict__ B,
             float* __restrict__ C,
             int M, int N, int K, int lda, int ldb, int ldc,
             long batchA, long batchB, long cOut, long cInn, int cH,
             float alpha)
{
    __shared__ uint32_t As[16][SPAD];   // [k][m], tf32 bits
    __shared__ uint32_t Bs[16][SPAD];   // [k][n], tf32 bits

    const int tid  = threadIdx.x;
    const int lane = tid & 31;
    const int warp = tid >> 5;
    const int warp_m = (warp & 3) * 32;  // 0,32,64,96
    const int warp_n = (warp >> 2) * 64; // 0,64

    const int z = blockIdx.z;
    A += (long)z * batchA;
    B += (long)z * batchB;
    const long coff = (long)(z / cH) * cOut + (long)(z % cH) * cInn;

    const int bn = blockIdx.x * 128;
    const int bm = blockIdx.y * 128;

    float acc[2][8][4];
    #pragma unroll
    for (int i = 0; i < 2; i++)
        #pragma unroll
        for (int j = 0; j < 8; j++)
            #pragma unroll
            for (int c = 0; c < 4; c++) acc[i][j][c] = 0.f;

    const int lg = lane >> 2;   // 0..7
    const int lk = lane & 3;    // 0..3

    for (int k0 = 0; k0 < K; k0 += 16) {
        // ---- load A tile (transpose into As[k][m]) ----
        #pragma unroll
        for (int p = 0; p < 2; p++) {
            int i = tid + p * 256;
            int m  = i >> 2;
            int kv = i & 3;
            float4 v = *(const float4*)&A[(long)(bm + m) * lda + k0 + kv * 4];
            As[kv*4+0][m] = to_tf32(v.x);
            As[kv*4+1][m] = to_tf32(v.y);
            As[kv*4+2][m] = to_tf32(v.z);
            As[kv*4+3][m] = to_tf32(v.w);
        }
        // ---- load B tile into Bs[k][n] ----
        if (TRANS_B) {
            #pragma unroll
            for (int p = 0; p < 2; p++) {
                int i = tid + p * 256;
                int n  = i >> 2;
                int kv = i & 3;
                float4 v = *(const float4*)&B[(long)(bn + n) * ldb + k0 + kv * 4];
                Bs[kv*4+0][n] = to_tf32(v.x);
                Bs[kv*4+1][n] = to_tf32(v.y);
                Bs[kv*4+2][n] = to_tf32(v.z);
                Bs[kv*4+3][n] = to_tf32(v.w);
            }
        } else {
            #pragma unroll
            for (int p = 0; p < 2; p++) {
                int i = tid + p * 256;
                int k  = i >> 5;
                int n4 = i & 31;
                float4 v = *(const float4*)&B[(long)(k0 + k) * ldb + bn + n4 * 4];
                uint4 u;
                u.x = to_tf32(v.x); u.y = to_tf32(v.y);
                u.z = to_tf32(v.z); u.w = to_tf32(v.w);
                *(uint4*)&Bs[k][n4 * 4] = u;
            }
        }
        __syncthreads();

        // ---- compute: two k8 steps ----
        #pragma unroll
        for (int ks = 0; ks < 16; ks += 8) {
            uint32_t af[2][4];
            uint32_t bf[8][2];
            #pragma unroll
            for (int i = 0; i < 2; i++) {
                int m = warp_m + i * 16 + lg;
                af[i][0] = As[ks + lk    ][m];
                af[i][1] = As[ks + lk    ][m + 8];
                af[i][2] = As[ks + lk + 4][m];
                af[i][3] = As[ks + lk + 4][m + 8];
            }
            #pragma unroll
            for (int j = 0; j < 8; j++) {
                int n = warp_n + j * 8 + lg;
                bf[j][0] = Bs[ks + lk    ][n];
                bf[j][1] = Bs[ks + lk + 4][n];
            }
            #pragma unroll
            for (int i = 0; i < 2; i++)
                #pragma unroll
                for (int j = 0; j < 8; j++)
                    mma_tf32(acc[i][j], af[i], bf[j]);
        }
        __syncthreads();
    }

    // ---- epilogue ----
    if (!SPLIT) {
        float* Cb = C + coff;
        #pragma unroll
        for (int i = 0; i < 2; i++) {
            long r0 = bm + warp_m + i * 16 + lg;
            #pragma unroll
            for (int j = 0; j < 8; j++) {
                int col = bn + warp_n + j * 8 + lk * 2;
                float2 o0 = make_float2(alpha * acc[i][j][0], alpha * acc[i][j][1]);
                float2 o1 = make_float2(alpha * acc[i][j][2], alpha * acc[i][j][3]);
                *(float2*)&Cb[r0 * ldc + col]       = o0;
                *(float2*)&Cb[(r0 + 8) * ldc + col] = o1;
            }
        }
    } else {
        // qkv scatter: block's 128 output cols lie within exactly one (sel, head)
        int sel = bn >> 11;
        int h   = (bn & 2047) >> 7;
        float* dst = (sel == 0) ? g_q : (sel == 1) ? g_k : g_v;
        #pragma unroll
        for (int i = 0; i < 2; i++) {
            int m = bm + warp_m + i * 16 + lg;
            int b = m >> 11;
            int t = m & 2047;
            long base = ((long)(b * HH + h) * TT + t) * DD;
            #pragma unroll
            for (int j = 0; j < 8; j++) {
                int d = (bn + warp_n + j * 8 + lk * 2) & 127;
                float2 o0 = make_float2(acc[i][j][0], acc[i][j][1]);
                float2 o1 = make_float2(acc[i][j][2], acc[i][j][3]);
                *(float2*)&dst[base + d]            = o0;
                *(float2*)&dst[base + 8 * DD + d]   = o1;
            }
        }
    }
}

// ---------------- RoPE (in place on g_q, g_k) ----------------
__global__ __launch_bounds__(256)
void rope_kernel(const float* __restrict__ cosb, const float* __restrict__ sinb)
{
    long idx = (long)blockIdx.x * blockDim.x + threadIdx.x;
    const long total = (long)BB * HH * TT * 64;
    if (idx >= total) return;
    int d = idx & 63;
    long r = idx >> 6;
    int t = (int)(r % TT);
    long base = r * DD + d;
    float c = cosb[t * DD + d];
    float s = sinb[t * DD + d];
    float q0 = g_q[base], q1 = g_q[base + 64];
    g_q[base]      = q0 * c - q1 * s;
    g_q[base + 64] = q1 * c + q0 * s;
    float k0 = g_k[base], k1 = g_k[base + 64];
    g_k[base]      = k0 * c - k1 * s;
    g_k[base + 64] = k1 * c + k0 * s;
}

// ---------------- row softmax over g_s ----------------
__global__ __launch_bounds__(256)
void softmax_kernel()
{
    long row = blockIdx.x;
    float* p = g_s + row * (long)TT;
    int tid = threadIdx.x;
    float v[8];
    float mx = -1e30f;
    #pragma unroll
    for (int i = 0; i < 8; i++) {
        v[i] = p[tid + i * 256];
        mx = fmaxf(mx, v[i]);
    }
    __shared__ float sm[8];
    #pragma unroll
    for (int o = 16; o; o >>= 1) mx = fmaxf(mx, __shfl_xor_sync(0xffffffffu, mx, o));
    if ((tid & 31) == 0) sm[tid >> 5] = mx;
    __syncthreads();
    float rowmax = sm[0];
    #pragma unroll
    for (int w = 1; w < 8; w++) rowmax = fmaxf(rowmax, sm[w]);
    __syncthreads();

    float sum = 0.f;
    #pragma unroll
    for (int i = 0; i < 8; i++) {
        v[i] = expf(v[i] - rowmax);
        sum += v[i];
    }
    #pragma unroll
    for (int o = 16; o; o >>= 1) sum += __shfl_xor_sync(0xffffffffu, sum, o);
    if ((tid & 31) == 0) sm[tid >> 5] = sum;
    __syncthreads();
    float rowsum = 0.f;
    #pragma unroll
    for (int w = 0; w < 8; w++) rowsum += sm[w];
    float inv = 1.f / rowsum;
    #pragma unroll
    for (int i = 0; i < 8; i++) p[tid + i * 256] = v[i] * inv;
}

// ---------------- launch ----------------
extern "C" void kernel_launch(void* const* d_in, const int* in_sizes, int n_in,
                              void* d_out, int out_size)
{
    const float* x     = (const float*)d_in[0];
    const float* cosb  = (const float*)d_in[1];
    const float* sinb  = (const float*)d_in[2];
    const float* Wqkv  = (const float*)d_in[3];
    const float* Wproj = (const float*)d_in[4];
    float* out = (float*)d_out;

    float *q, *k, *v, *s, *y;
    cudaGetSymbolAddress((void**)&q, g_q);
    cudaGetSymbolAddress((void**)&k, g_k);
    cudaGetSymbolAddress((void**)&v, g_v);
    cudaGetSymbolAddress((void**)&s, g_s);
    cudaGetSymbolAddress((void**)&y, g_y);

    const float scale = 0.08838834764831845f;  // 1/sqrt(128)

    // 1) qkv = x @ W_qkv, scattered to g_q/g_k/g_v [B,H,T,D]
    mmagemm<0,1><<<dim3(48, 32, 1), 256>>>(
        x, Wqkv, nullptr,
        4096, 6144, 2048, 2048, 6144, 0,
        0L, 0L, 0L, 0L, 1, 1.0f);

    // 2) RoPE in place on q, k
    rope_kernel<<<16384, 256>>>(cosb, sinb);

    // 3) scores = scale * Q @ K^T  (batched over B*H = 32)
    mmagemm<1,0><<<dim3(16, 16, BH), 256>>>(
        q, k, s,
        2048, 2048, 128, 128, 128, 2048,
        (long)TT * DD, (long)TT * DD, (long)TT * TT, 0L, 1, scale);

    // 4) softmax rows
    softmax_kernel<<<BH * TT, 256>>>();

    // 5) y = attn @ V, written straight into [B,T,H*D] layout
    mmagemm<0,0><<<dim3(1, 16, BH), 256>>>(
        s, v, y,
        2048, 128, 2048, 2048, 128, 2048,
        (long)TT * TT, (long)TT * DD, (long)TT * CC, 128L, HH, 1.0f);

    // 6) out = y @ W_proj
    mmagemm<0,0><<<dim3(16, 32, 1), 256>>>(
        y, Wproj, out,
        4096, 2048, 2048, 2048, 2048, 2048,
        0L, 0L, 0L, 0L, 1, 1.0f);
}

// round 4
// speedup vs baseline: 4.5471x; 2.0327x over previous
#include <cuda_runtime.h>
#include <cuda_fp16.h>
#include <stdint.h>
#include <math.h>

// Problem constants
#define BB 2
#define TT 2048
#define CC 2048
#define HH 16
#define DD 128
#define BH (BB*HH)          // 32

// ---------------- scratch (device globals, no allocation) ----------------
// half buffers declared as uint4 for 16B alignment (cp.async requirement)
__device__ uint4 g_xh4   [(size_t)BB*TT*CC/8];        // x as half
__device__ uint4 g_wqkvT4[(size_t)3*CC*CC/8];         // W_qkv^T half (6144 x 2048)
__device__ uint4 g_wprojT4[(size_t)CC*CC/8];          // W_proj^T half
__device__ uint4 g_qh4   [(size_t)BB*HH*TT*DD/8];     // q half [B,H,T,D] (post-rope)
__device__ uint4 g_kh4   [(size_t)BB*HH*TT*DD/8];     // k half [B,H,T,D] (post-rope)
__device__ uint4 g_vh4   [(size_t)BB*HH*DD*TT/8];     // v half [B,H,D,T] (transposed)
__device__ uint4 g_ph4   [(size_t)BH*TT*TT/8];        // probs half
__device__ uint4 g_yh4   [(size_t)BB*TT*CC/8];        // y half [B*T, C]
__device__ float g_q[(size_t)BB*HH*TT*DD];            // raw fp32 q (pre-rope)
__device__ float g_k[(size_t)BB*HH*TT*DD];            // raw fp32 k (pre-rope)
__device__ float g_s[(size_t)BH*TT*TT];               // scores fp32

// ---------------- helpers ----------------
__device__ __forceinline__ void cpa16(uint32_t dst, const void* src) {
    asm volatile("cp.async.cg.shared.global [%0], [%1], 16;" :: "r"(dst), "l"(src));
}

__device__ __forceinline__ void mma_h(float* d, const uint32_t* a, const uint32_t* b) {
    asm volatile(
        "mma.sync.aligned.m16n8k16.row.col.f32.f16.f16.f32 "
        "{%0,%1,%2,%3}, {%4,%5,%6,%7}, {%8,%9}, {%0,%1,%2,%3};"
        : "+f"(d[0]), "+f"(d[1]), "+f"(d[2]), "+f"(d[3])
        : "r"(a[0]), "r"(a[1]), "r"(a[2]), "r"(a[3]),
          "r"(b[0]), "r"(b[1]));
}

// ---------------- fp16 tensor-core GEMM ----------------
// C = alpha * A * B^T.  A: (M x K) half row-major lda; B: (N x K) half row-major ldb.
// Block 128x128, K-tile 32 halves, 256 threads, 8 warps (4M x 2N), warp tile 32x64.
// Smem row = 32 halves (64B) padded to 80B (20 words): LDS word addr 20*lg+lk is
// conflict-free mod 32.
// EPI 0: fp32 C + z*cOut, *alpha
// EPI 1: qkv scatter -> g_q/g_k fp32 [B,H,T,D], v half transposed [B,H,D,T]
// EPI 2: y half at (b*T+row)*C + h*128 + col   (z = b*HH + h)
template<int EPI>
__global__ __launch_bounds__(256)
void hgemm(const __half* __restrict__ A, const __half* __restrict__ B,
           float* __restrict__ C,
           int K, int lda, int ldb, int ldc,
           long batchA, long batchB, long cOut, float alpha)
{
    __shared__ uint32_t As[2][128][20];
    __shared__ uint32_t Bs[2][128][20];

    const int tid  = threadIdx.x;
    const int lane = tid & 31;
    const int warp = tid >> 5;
    const int warp_m = (warp & 3) * 32;
    const int warp_n = (warp >> 2) * 64;
    const int lg = lane >> 2;
    const int lk = lane & 3;

    const int z = blockIdx.z;
    const __half* Ab = A + (long)z * batchA;
    const __half* Bb = B + (long)z * batchB;
    const int bn = blockIdx.x * 128;
    const int bm = blockIdx.y * 128;

    float acc[2][8][4];
    #pragma unroll
    for (int i = 0; i < 2; i++)
        #pragma unroll
        for (int j = 0; j < 8; j++)
            #pragma unroll
            for (int c = 0; c < 4; c++) acc[i][j][c] = 0.f;

    const uint32_t sA0 = (uint32_t)__cvta_generic_to_shared(&As[0][0][0]);
    const uint32_t sB0 = (uint32_t)__cvta_generic_to_shared(&Bs[0][0][0]);
    const int nt = K >> 5;

    // issue loads for tile t into stage st
    auto ldtile = [&](int t, int st) {
        uint32_t sa = sA0 + st * 10240u;
        uint32_t sb = sB0 + st * 10240u;
        int k0 = t << 5;
        #pragma unroll
        for (int p = 0; p < 2; p++) {
            int ch  = tid + p * 256;
            int row = ch >> 2;
            int c   = ch & 3;
            cpa16(sa + row * 80 + c * 16, Ab + (long)(bm + row) * lda + k0 + c * 8);
            cpa16(sb + row * 80 + c * 16, Bb + (long)(bn + row) * ldb + k0 + c * 8);
        }
        asm volatile("cp.async.commit_group;" ::: "memory");
    };

    ldtile(0, 0);

    for (int it = 0; it < nt; it++) {
        int st = it & 1;
        if (it + 1 < nt) {
            ldtile(it + 1, st ^ 1);
            asm volatile("cp.async.wait_group 1;" ::: "memory");
        } else {
            asm volatile("cp.async.wait_group 0;" ::: "memory");
        }
        __syncthreads();

        #pragma unroll
        for (int ks = 0; ks < 2; ks++) {
            int ko = ks * 8;
            uint32_t af[2][4];
            uint32_t bf[8][2];
            #pragma unroll
            for (int i = 0; i < 2; i++) {
                int m = warp_m + i * 16 + lg;
                af[i][0] = As[st][m    ][ko + lk];
                af[i][1] = As[st][m + 8][ko + lk];
                af[i][2] = As[st][m    ][ko + lk + 4];
                af[i][3] = As[st][m + 8][ko + lk + 4];
            }
            #pragma unroll
            for (int j = 0; j < 8; j++) {
                int n = warp_n + j * 8 + lg;
                bf[j][0] = Bs[st][n][ko + lk];
                bf[j][1] = Bs[st][n][ko + lk + 4];
            }
            #pragma unroll
            for (int i = 0; i < 2; i++)
                #pragma unroll
                for (int j = 0; j < 8; j++)
                    mma_h(acc[i][j], af[i], bf[j]);
        }
        __syncthreads();
    }

    // ---- epilogue ----
    if (EPI == 0) {
        float* Cb = C + (long)z * cOut;
        #pragma unroll
        for (int i = 0; i < 2; i++) {
            long r0 = bm + warp_m + i * 16 + lg;
            #pragma unroll
            for (int j = 0; j < 8; j++) {
                int col = bn + warp_n + j * 8 + lk * 2;
                *(float2*)&Cb[r0 * ldc + col] =
                    make_float2(alpha * acc[i][j][0], alpha * acc[i][j][1]);
                *(float2*)&Cb[(r0 + 8) * ldc + col] =
                    make_float2(alpha * acc[i][j][2], alpha * acc[i][j][3]);
            }
        }
    } else if (EPI == 1) {
        int sel = bn >> 11;
        int h   = (bn & 2047) >> 7;
        #pragma unroll
        for (int i = 0; i < 2; i++) {
            int rowm = bm + warp_m + i * 16 + lg;
            int b = rowm >> 11;
            int t = rowm & 2047;
            if (sel < 2) {
                float* dst = sel ? g_k : g_q;
                long base = ((long)(b * HH + h) * TT + t) * DD;
                #pragma unroll
                for (int j = 0; j < 8; j++) {
                    int d = warp_n + j * 8 + lk * 2;
                    *(float2*)&dst[base + d] =
                        make_float2(acc[i][j][0], acc[i][j][1]);
                    *(float2*)&dst[base + 8 * DD + d] =
                        make_float2(acc[i][j][2], acc[i][j][3]);
                }
            } else {
                __half* vh = (__half*)g_vh4;
                long vb = (long)(b * HH + h) * DD * TT;
                #pragma unroll
                for (int j = 0; j < 8; j++) {
                    int d = warp_n + j * 8 + lk * 2;
                    vh[vb + (long)d       * TT + t]     = __float2half_rn(acc[i][j][0]);
                    vh[vb + (long)(d + 1) * TT + t]     = __float2half_rn(acc[i][j][1]);
                    vh[vb + (long)d       * TT + t + 8] = __float2half_rn(acc[i][j][2]);
                    vh[vb + (long)(d + 1) * TT + t + 8] = __float2half_rn(acc[i][j][3]);
                }
            }
        }
    } else { // EPI == 2
        __half* yh = (__half*)g_yh4;
        int h = z % HH, b = z / HH;
        #pragma unroll
        for (int i = 0; i < 2; i++) {
            int rowm = bm + warp_m + i * 16 + lg;
            long base = ((long)(b * TT + rowm)) * CC + h * DD;
            #pragma unroll
            for (int j = 0; j < 8; j++) {
                int col = warp_n + j * 8 + lk * 2;
                *(__half2*)&yh[base + col] =
                    __floats2half2_rn(acc[i][j][0], acc[i][j][1]);
                *(__half2*)&yh[base + 8 * CC + col] =
                    __floats2half2_rn(acc[i][j][2], acc[i][j][3]);
            }
        }
    }
}

// ---------------- prepass: fp32 -> fp16 ----------------
__global__ __launch_bounds__(256)
void f2h_kernel(const float4* __restrict__ src, uint2* __restrict__ dst, int n4)
{
    int i = blockIdx.x * blockDim.x + threadIdx.x;
    if (i >= n4) return;
    float4 v = src[i];
    uint2 o;
    __half2 lo = __floats2half2_rn(v.x, v.y);
    __half2 hi = __floats2half2_rn(v.z, v.w);
    o.x = *(uint32_t*)&lo;
    o.y = *(uint32_t*)&hi;
    dst[i] = o;
}

__global__ __launch_bounds__(256)
void transpose_h_kernel(const float* __restrict__ src, __half* __restrict__ dst,
                        int R, int C)
{
    __shared__ float t[32][33];
    int c0 = blockIdx.x * 32, r0 = blockIdx.y * 32;
    int tx = threadIdx.x, ty = threadIdx.y;   // (32, 8)
    #pragma unroll
    for (int i = 0; i < 32; i += 8)
        t[ty + i][tx] = src[(long)(r0 + ty + i) * C + c0 + tx];
    __syncthreads();
    #pragma unroll
    for (int i = 0; i < 32; i += 8)
        dst[(long)(c0 + ty + i) * R + r0 + tx] = __float2half_rn(t[tx][ty + i]);
}

// ---------------- RoPE: fp32 q/k -> rotated fp16 qh/kh ----------------
__global__ __launch_bounds__(256)
void rope_kernel(const float* __restrict__ cosb, const float* __restrict__ sinb)
{
    long idx = (long)blockIdx.x * blockDim.x + threadIdx.x;
    const long total = (long)BB * HH * TT * 64;
    if (idx >= total) return;
    int d = idx & 63;
    long r = idx >> 6;
    int t = (int)(r % TT);
    long base = r * DD + d;
    float c = cosb[t * DD + d];
    float s = sinb[t * DD + d];
    __half* qh = (__half*)g_qh4;
    __half* kh = (__half*)g_kh4;
    float q0 = g_q[base], q1 = g_q[base + 64];
    qh[base]      = __float2half_rn(q0 * c - q1 * s);
    qh[base + 64] = __float2half_rn(q1 * c + q0 * s);
    float k0 = g_k[base], k1 = g_k[base + 64];
    kh[base]      = __float2half_rn(k0 * c - k1 * s);
    kh[base + 64] = __float2half_rn(k1 * c + k0 * s);
}

// ---------------- row softmax: fp32 scores -> fp16 probs ----------------
__global__ __launch_bounds__(256)
void softmax_kernel()
{
    long row = blockIdx.x;
    const float* p = g_s + row * (long)TT;
    __half* ph = (__half*)g_ph4 + row * (long)TT;
    int tid = threadIdx.x;
    float v[8];
    float mx = -1e30f;
    #pragma unroll
    for (int i = 0; i < 8; i++) {
        v[i] = p[tid + i * 256];
        mx = fmaxf(mx, v[i]);
    }
    __shared__ float sm[8];
    #pragma unroll
    for (int o = 16; o; o >>= 1) mx = fmaxf(mx, __shfl_xor_sync(0xffffffffu, mx, o));
    if ((tid & 31) == 0) sm[tid >> 5] = mx;
    __syncthreads();
    float rowmax = sm[0];
    #pragma unroll
    for (int w = 1; w < 8; w++) rowmax = fmaxf(rowmax, sm[w]);
    __syncthreads();

    float sum = 0.f;
    #pragma unroll
    for (int i = 0; i < 8; i++) {
        v[i] = expf(v[i] - rowmax);
        sum += v[i];
    }
    #pragma unroll
    for (int o = 16; o; o >>= 1) sum += __shfl_xor_sync(0xffffffffu, sum, o);
    if ((tid & 31) == 0) sm[tid >> 5] = sum;
    __syncthreads();
    float rowsum = 0.f;
    #pragma unroll
    for (int w = 0; w < 8; w++) rowsum += sm[w];
    float inv = 1.f / rowsum;
    #pragma unroll
    for (int i = 0; i < 8; i++) ph[tid + i * 256] = __float2half_rn(v[i] * inv);
}

// ---------------- launch ----------------
extern "C" void kernel_launch(void* const* d_in, const int* in_sizes, int n_in,
                              void* d_out, int out_size)
{
    const float* x     = (const float*)d_in[0];
    const float* cosb  = (const float*)d_in[1];
    const float* sinb  = (const float*)d_in[2];
    const float* Wqkv  = (const float*)d_in[3];
    const float* Wproj = (const float*)d_in[4];
    float* out = (float*)d_out;

    void *xh, *wqkvT, *wprojT, *qh, *kh, *vh, *ph, *yh;
    float *s;
    cudaGetSymbolAddress(&xh,     g_xh4);
    cudaGetSymbolAddress(&wqkvT,  g_wqkvT4);
    cudaGetSymbolAddress(&wprojT, g_wprojT4);
    cudaGetSymbolAddress(&qh, g_qh4);
    cudaGetSymbolAddress(&kh, g_kh4);
    cudaGetSymbolAddress(&vh, g_vh4);
    cudaGetSymbolAddress(&ph, g_ph4);
    cudaGetSymbolAddress(&yh, g_yh4);
    cudaGetSymbolAddress((void**)&s, g_s);

    const float scale = 0.08838834764831845f;  // 1/sqrt(128)

    // 0) prepass: x -> half; W_qkv^T, W_proj^T -> half
    {
        int n4 = (BB * TT * CC) / 4;
        f2h_kernel<<<(n4 + 255) / 256, 256>>>((const float4*)x, (uint2*)xh, n4);
        transpose_h_kernel<<<dim3(3 * CC / 32, CC / 32), dim3(32, 8)>>>(Wqkv,  (__half*)wqkvT,  CC, 3 * CC);
        transpose_h_kernel<<<dim3(CC / 32,     CC / 32), dim3(32, 8)>>>(Wproj, (__half*)wprojT, CC, CC);
    }

    // 1) qkv = x @ W_qkv  -> q,k fp32 [B,H,T,D]; v half [B,H,D,T]
    hgemm<1><<<dim3(48, 32, 1), 256>>>(
        (const __half*)xh, (const __half*)wqkvT, nullptr,
        2048, 2048, 2048, 0,
        0L, 0L, 0L, 1.0f);

    // 2) RoPE -> qh, kh (half)
    rope_kernel<<<16384, 256>>>(cosb, sinb);

    // 3) scores = scale * Q @ K^T -> g_s fp32 (batched over B*H)
    hgemm<0><<<dim3(16, 16, BH), 256>>>(
        (const __half*)qh, (const __half*)kh, s,
        128, 128, 128, 2048,
        (long)TT * DD, (long)TT * DD, (long)TT * TT, scale);

    // 4) softmax -> probs half
    softmax_kernel<<<BH * TT, 256>>>();

    // 5) y = P @ V -> yh half [B*T, C]
    hgemm<2><<<dim3(1, 16, BH), 256>>>(
        (const __half*)ph, (const __half*)vh, nullptr,
        2048, 2048, 2048, 0,
        (long)TT * TT, (long)DD * TT, 0L, 1.0f);

    // 6) out = y @ W_proj -> fp32
    hgemm<0><<<dim3(16, 32, 1), 256>>>(
        (const __half*)yh, (const __half*)wprojT, out,
        2048, 2048, 2048, 2048,
        0L, 0L, 0L, 1.0f);
}

// round 5
// speedup vs baseline: 4.6894x; 1.0313x over previous
#include <cuda_runtime.h>
#include <cuda_fp16.h>
#include <stdint.h>
#include <math.h>

// Problem constants
#define BB 2
#define TT 2048
#define CC 2048
#define HH 16
#define DD 128
#define BH (BB*HH)          // 32

// ---------------- scratch (device globals, no allocation) ----------------
__device__ uint4 g_xh4   [(size_t)BB*TT*CC/8];        // x as half
__device__ uint4 g_wqkvT4[(size_t)3*CC*CC/8];         // W_qkv^T half (6144 x 2048)
__device__ uint4 g_wprojT4[(size_t)CC*CC/8];          // W_proj^T half
__device__ uint4 g_qh4   [(size_t)BB*HH*TT*DD/8];     // q half [B,H,T,D] (post-rope)
__device__ uint4 g_kh4   [(size_t)BB*HH*TT*DD/8];     // k half [B,H,T,D] (post-rope)
__device__ uint4 g_vh4   [(size_t)BB*HH*DD*TT/8];     // v half [B,H,D,T] (transposed)
__device__ uint4 g_ph4   [(size_t)BH*TT*TT/8];        // probs half
__device__ uint4 g_yh4   [(size_t)BB*TT*CC/8];        // y half [B*T, C]
__device__ float g_q[(size_t)BB*HH*TT*DD];            // raw fp32 q (pre-rope)
__device__ float g_k[(size_t)BB*HH*TT*DD];            // raw fp32 k (pre-rope)
__device__ float g_s[(size_t)BH*TT*TT];               // scores fp32

// ---------------- helpers ----------------
__device__ __forceinline__ void cpa16(uint32_t dst, const void* src) {
    asm volatile("cp.async.cg.shared.global [%0], [%1], 16;" :: "r"(dst), "l"(src));
}

__device__ __forceinline__ void ldsm4(uint32_t* r, uint32_t addr) {
    asm volatile("ldmatrix.sync.aligned.m8n8.x4.shared.b16 {%0,%1,%2,%3}, [%4];"
                 : "=r"(r[0]), "=r"(r[1]), "=r"(r[2]), "=r"(r[3]) : "r"(addr));
}

__device__ __forceinline__ void mma_h(float* d, const uint32_t* a, const uint32_t* b) {
    asm volatile(
        "mma.sync.aligned.m16n8k16.row.col.f32.f16.f16.f32 "
        "{%0,%1,%2,%3}, {%4,%5,%6,%7}, {%8,%9}, {%0,%1,%2,%3};"
        : "+f"(d[0]), "+f"(d[1]), "+f"(d[2]), "+f"(d[3])
        : "r"(a[0]), "r"(a[1]), "r"(a[2]), "r"(a[3]),
          "r"(b[0]), "r"(b[1]));
}

// ---------------- fp16 tensor-core GEMM (ldmatrix + 3-stage cp.async) --------
// C = alpha * A * B^T.  A: (M x K) half row-major lda; B: (N x K) half row-major.
// Block 128x128, K-tile 32 halves (64B/row), 256 threads, 8 warps (4M x 2N),
// warp tile 32x64. Smem: swizzled 64B rows, chunk ^= (row & 3); 3 stages,
// 16KB/stage -> 48KB static smem. Conflict-free for STS.128 and LDSM.
// EPI 0: fp32 C + z*cOut, *alpha
// EPI 1: qkv scatter -> g_q/g_k fp32 [B,H,T,D], v half transposed [B,H,D,T]
// EPI 2: y half at (b*T+row)*C + h*128 + col   (z = b*HH + h)
#define STG_BYTES 16384u
template<int EPI>
__global__ __launch_bounds__(256)
void hgemm(const __half* __restrict__ A, const __half* __restrict__ B,
           float* __restrict__ C,
           int K, int lda, int ldb, int ldc,
           long batchA, long batchB, long cOut, float alpha)
{
    __shared__ __align__(128) char smem[3 * STG_BYTES];   // 48KB

    const int tid  = threadIdx.x;
    const int lane = tid & 31;
    const int warp = tid >> 5;
    const int warp_m = (warp & 3) * 32;
    const int warp_n = (warp >> 2) * 64;
    const int lg = lane >> 2;
    const int lk = lane & 3;

    const int z = blockIdx.z;
    const __half* Ab = A + (long)z * batchA;
    const __half* Bb = B + (long)z * batchB;
    const int bn = blockIdx.x * 128;
    const int bm = blockIdx.y * 128;

    float acc[2][8][4];
    #pragma unroll
    for (int i = 0; i < 2; i++)
        #pragma unroll
        for (int j = 0; j < 8; j++)
            #pragma unroll
            for (int c = 0; c < 4; c++) acc[i][j][c] = 0.f;

    const uint32_t s0 = (uint32_t)__cvta_generic_to_shared(smem);
    const int nt = K >> 5;

    // ---- cp.async tile loader: A at stage base, B at stage base + 8KB ----
    // store pattern: thread handles (row = tid>>2 (+64), chunk = tid&3)
    const int strow = tid >> 2;      // 0..63
    const int stc   = tid & 3;
    auto ldtile = [&](int t, int st) {
        uint32_t base = s0 + (uint32_t)st * STG_BYTES;
        int k0 = t << 5;
        #pragma unroll
        for (int p = 0; p < 2; p++) {
            int row = strow + p * 64;
            uint32_t sw = (uint32_t)(row * 64 + ((stc ^ (row & 3)) << 4));
            cpa16(base + sw,         Ab + (long)(bm + row) * lda + k0 + stc * 8);
            cpa16(base + 8192u + sw, Bb + (long)(bn + row) * ldb + k0 + stc * 8);
        }
        asm volatile("cp.async.commit_group;" ::: "memory");
    };

    // ---- ldmatrix per-lane row precompute ----
    // A x4: lanes 0-15 -> rows m..m+15 (chunk kc), 16-31 -> same rows (chunk kc+1)
    const int rowA  = warp_m + (lane & 15);
    const int chA   = lane >> 4;              // 0/1 within k16
    // B x4: lanes 0-7 n0-7/kc, 8-15 n0-7/kc+1, 16-23 n8-15/kc, 24-31 n8-15/kc+1
    const int rowB  = warp_n + (lane & 7) + ((lane >> 4) << 3);
    const int chB   = (lane >> 3) & 1;

    // prologue: stages 0,1
    ldtile(0, 0);
    if (nt > 1) ldtile(1, 1);

    for (int it = 0; it < nt; it++) {
        if (it + 1 < nt) asm volatile("cp.async.wait_group 1;" ::: "memory");
        else             asm volatile("cp.async.wait_group 0;" ::: "memory");
        __syncthreads();   // tile it ready; all warps done with stage (it+2)%3's old data

        if (it + 2 < nt) ldtile(it + 2, (it + 2) % 3);

        uint32_t abase = s0 + (uint32_t)(it % 3) * STG_BYTES;
        uint32_t bbase = abase + 8192u;

        #pragma unroll
        for (int ks = 0; ks < 2; ks++) {
            int kc = ks * 2;
            uint32_t af[2][4];
            #pragma unroll
            for (int i = 0; i < 2; i++) {
                int r = rowA + i * 16;
                ldsm4(af[i], abase + r * 64 + (((kc + chA) ^ (r & 3)) << 4));
            }
            uint32_t bf[8][2];
            #pragma unroll
            for (int j4 = 0; j4 < 4; j4++) {
                int r = rowB + j4 * 16;
                uint32_t t4[4];
                ldsm4(t4, bbase + r * 64 + (((kc + chB) ^ (r & 3)) << 4));
                bf[j4 * 2][0]     = t4[0];
                bf[j4 * 2][1]     = t4[1];
                bf[j4 * 2 + 1][0] = t4[2];
                bf[j4 * 2 + 1][1] = t4[3];
            }
            #pragma unroll
            for (int i = 0; i < 2; i++)
                #pragma unroll
                for (int j = 0; j < 8; j++)
                    mma_h(acc[i][j], af[i], bf[j]);
        }
        __syncthreads();
    }

    // ---- epilogue ----
    if (EPI == 0) {
        float* Cb = C + (long)z * cOut;
        #pragma unroll
        for (int i = 0; i < 2; i++) {
            long r0 = bm + warp_m + i * 16 + lg;
            #pragma unroll
            for (int j = 0; j < 8; j++) {
                int col = bn + warp_n + j * 8 + lk * 2;
                *(float2*)&Cb[r0 * ldc + col] =
                    make_float2(alpha * acc[i][j][0], alpha * acc[i][j][1]);
                *(float2*)&Cb[(r0 + 8) * ldc + col] =
                    make_float2(alpha * acc[i][j][2], alpha * acc[i][j][3]);
            }
        }
    } else if (EPI == 1) {
        int sel = bn >> 11;
        int h   = (bn & 2047) >> 7;
        #pragma unroll
        for (int i = 0; i < 2; i++) {
            int rowm = bm + warp_m + i * 16 + lg;
            int b = rowm >> 11;
            int t = rowm & 2047;
            if (sel < 2) {
                float* dst = sel ? g_k : g_q;
                long base = ((long)(b * HH + h) * TT + t) * DD;
                #pragma unroll
                for (int j = 0; j < 8; j++) {
                    int d = warp_n + j * 8 + lk * 2;
                    *(float2*)&dst[base + d] =
                        make_float2(acc[i][j][0], acc[i][j][1]);
                    *(float2*)&dst[base + 8 * DD + d] =
                        make_float2(acc[i][j][2], acc[i][j][3]);
                }
            } else {
                __half* vh = (__half*)g_vh4;
                long vb = (long)(b * HH + h) * DD * TT;
                #pragma unroll
                for (int j = 0; j < 8; j++) {
                    int d = warp_n + j * 8 + lk * 2;
                    vh[vb + (long)d       * TT + t]     = __float2half_rn(acc[i][j][0]);
                    vh[vb + (long)(d + 1) * TT + t]     = __float2half_rn(acc[i][j][1]);
                    vh[vb + (long)d       * TT + t + 8] = __float2half_rn(acc[i][j][2]);
                    vh[vb + (long)(d + 1) * TT + t + 8] = __float2half_rn(acc[i][j][3]);
                }
            }
        }
    } else { // EPI == 2
        __half* yh = (__half*)g_yh4;
        int h = z % HH, b = z / HH;
        #pragma unroll
        for (int i = 0; i < 2; i++) {
            int rowm = bm + warp_m + i * 16 + lg;
            long base = ((long)(b * TT + rowm)) * CC + h * DD;
            #pragma unroll
            for (int j = 0; j < 8; j++) {
                int col = warp_n + j * 8 + lk * 2;
                *(__half2*)&yh[base + col] =
                    __floats2half2_rn(acc[i][j][0], acc[i][j][1]);
                *(__half2*)&yh[base + 8 * CC + col] =
                    __floats2half2_rn(acc[i][j][2], acc[i][j][3]);
            }
        }
    }
}

// ---------------- prepass: fp32 -> fp16 ----------------
__global__ __launch_bounds__(256)
void f2h_kernel(const float4* __restrict__ src, uint2* __restrict__ dst, int n4)
{
    int i = blockIdx.x * blockDim.x + threadIdx.x;
    if (i >= n4) return;
    float4 v = src[i];
    uint2 o;
    __half2 lo = __floats2half2_rn(v.x, v.y);
    __half2 hi = __floats2half2_rn(v.z, v.w);
    o.x = *(uint32_t*)&lo;
    o.y = *(uint32_t*)&hi;
    dst[i] = o;
}

__global__ __launch_bounds__(256)
void transpose_h_kernel(const float* __restrict__ src, __half* __restrict__ dst,
                        int R, int C)
{
    __shared__ float t[32][33];
    int c0 = blockIdx.x * 32, r0 = blockIdx.y * 32;
    int tx = threadIdx.x, ty = threadIdx.y;   // (32, 8)
    #pragma unroll
    for (int i = 0; i < 32; i += 8)
        t[ty + i][tx] = src[(long)(r0 + ty + i) * C + c0 + tx];
    __syncthreads();
    #pragma unroll
    for (int i = 0; i < 32; i += 8)
        dst[(long)(c0 + ty + i) * R + r0 + tx] = __float2half_rn(t[tx][ty + i]);
}

// ---------------- RoPE: fp32 q/k -> rotated fp16 qh/kh ----------------
__global__ __launch_bounds__(256)
void rope_kernel(const float* __restrict__ cosb, const float* __restrict__ sinb)
{
    long idx = (long)blockIdx.x * blockDim.x + threadIdx.x;
    const long total = (long)BB * HH * TT * 64;
    if (idx >= total) return;
    int d = idx & 63;
    long r = idx >> 6;
    int t = (int)(r % TT);
    long base = r * DD + d;
    float c = cosb[t * DD + d];
    float s = sinb[t * DD + d];
    __half* qh = (__half*)g_qh4;
    __half* kh = (__half*)g_kh4;
    float q0 = g_q[base], q1 = g_q[base + 64];
    qh[base]      = __float2half_rn(q0 * c - q1 * s);
    qh[base + 64] = __float2half_rn(q1 * c + q0 * s);
    float k0 = g_k[base], k1 = g_k[base + 64];
    kh[base]      = __float2half_rn(k0 * c - k1 * s);
    kh[base + 64] = __float2half_rn(k1 * c + k0 * s);
}

// ---------------- row softmax: fp32 scores -> fp16 probs ----------------
__global__ __launch_bounds__(256)
void softmax_kernel()
{
    long row = blockIdx.x;
    const float* p = g_s + row * (long)TT;
    __half* ph = (__half*)g_ph4 + row * (long)TT;
    int tid = threadIdx.x;
    float v[8];
    float mx = -1e30f;
    #pragma unroll
    for (int i = 0; i < 8; i++) {
        v[i] = p[tid + i * 256];
        mx = fmaxf(mx, v[i]);
    }
    __shared__ float sm[8];
    #pragma unroll
    for (int o = 16; o; o >>= 1) mx = fmaxf(mx, __shfl_xor_sync(0xffffffffu, mx, o));
    if ((tid & 31) == 0) sm[tid >> 5] = mx;
    __syncthreads();
    float rowmax = sm[0];
    #pragma unroll
    for (int w = 1; w < 8; w++) rowmax = fmaxf(rowmax, sm[w]);
    __syncthreads();

    float sum = 0.f;
    #pragma unroll
    for (int i = 0; i < 8; i++) {
        v[i] = expf(v[i] - rowmax);
        sum += v[i];
    }
    #pragma unroll
    for (int o = 16; o; o >>= 1) sum += __shfl_xor_sync(0xffffffffu, sum, o);
    if ((tid & 31) == 0) sm[tid >> 5] = sum;
    __syncthreads();
    float rowsum = 0.f;
    #pragma unroll
    for (int w = 0; w < 8; w++) rowsum += sm[w];
    float inv = 1.f / rowsum;
    #pragma unroll
    for (int i = 0; i < 8; i++) ph[tid + i * 256] = __float2half_rn(v[i] * inv);
}

// ---------------- launch ----------------
extern "C" void kernel_launch(void* const* d_in, const int* in_sizes, int n_in,
                              void* d_out, int out_size)
{
    const float* x     = (const float*)d_in[0];
    const float* cosb  = (const float*)d_in[1];
    const float* sinb  = (const float*)d_in[2];
    const float* Wqkv  = (const float*)d_in[3];
    const float* Wproj = (const float*)d_in[4];
    float* out = (float*)d_out;

    void *xh, *wqkvT, *wprojT, *qh, *kh, *vh, *ph, *yh;
    float *s;
    cudaGetSymbolAddress(&xh,     g_xh4);
    cudaGetSymbolAddress(&wqkvT,  g_wqkvT4);
    cudaGetSymbolAddress(&wprojT, g_wprojT4);
    cudaGetSymbolAddress(&qh, g_qh4);
    cudaGetSymbolAddress(&kh, g_kh4);
    cudaGetSymbolAddress(&vh, g_vh4);
    cudaGetSymbolAddress(&ph, g_ph4);
    cudaGetSymbolAddress(&yh, g_yh4);
    cudaGetSymbolAddress((void**)&s, g_s);

    const float scale = 0.08838834764831845f;  // 1/sqrt(128)

    // 0) prepass: x -> half; W_qkv^T, W_proj^T -> half
    {
        int n4 = (BB * TT * CC) / 4;
        f2h_kernel<<<(n4 + 255) / 256, 256>>>((const float4*)x, (uint2*)xh, n4);
        transpose_h_kernel<<<dim3(3 * CC / 32, CC / 32), dim3(32, 8)>>>(Wqkv,  (__half*)wqkvT,  CC, 3 * CC);
        transpose_h_kernel<<<dim3(CC / 32,     CC / 32), dim3(32, 8)>>>(Wproj, (__half*)wprojT, CC, CC);
    }

    // 1) qkv = x @ W_qkv  -> q,k fp32 [B,H,T,D]; v half [B,H,D,T]
    hgemm<1><<<dim3(48, 32, 1), 256>>>(
        (const __half*)xh, (const __half*)wqkvT, nullptr,
        2048, 2048, 2048, 0,
        0L, 0L, 0L, 1.0f);

    // 2) RoPE -> qh, kh (half)
    rope_kernel<<<16384, 256>>>(cosb, sinb);

    // 3) scores = scale * Q @ K^T -> g_s fp32 (batched over B*H)
    hgemm<0><<<dim3(16, 16, BH), 256>>>(
        (const __half*)qh, (const __half*)kh, s,
        128, 128, 128, 2048,
        (long)TT * DD, (long)TT * DD, (long)TT * TT, scale);

    // 4) softmax -> probs half
    softmax_kernel<<<BH * TT, 256>>>();

    // 5) y = P @ V -> yh half [B*T, C]
    hgemm<2><<<dim3(1, 16, BH), 256>>>(
        (const __half*)ph, (const __half*)vh, nullptr,
        2048, 2048, 2048, 0,
        (long)TT * TT, (long)DD * TT, 0L, 1.0f);

    // 6) out = y @ W_proj -> fp32
    hgemm<0><<<dim3(16, 32, 1), 256>>>(
        (const __half*)yh, (const __half*)wprojT, out,
        2048, 2048, 2048, 2048,
        0L, 0L, 0L, 1.0f);
}

// round 6
// speedup vs baseline: 4.8490x; 1.0340x over previous
#include <cuda_runtime.h>
#include <cuda_fp16.h>
#include <stdint.h>
#include <math.h>

// Problem constants
#define BB 2
#define TT 2048
#define CC 2048
#define HH 16
#define DD 128
#define BH (BB*HH)          // 32

// ---------------- scratch (device globals, no allocation) ----------------
__device__ uint4 g_xh4   [(size_t)BB*TT*CC/8];        // x as half
__device__ uint4 g_wqkvT4[(size_t)3*CC*CC/8];         // W_qkv^T half (6144 x 2048)
__device__ uint4 g_wprojT4[(size_t)CC*CC/8];          // W_proj^T half
__device__ uint4 g_qh4   [(size_t)BB*HH*TT*DD/8];     // q half [B,H,T,D] (post-rope)
__device__ uint4 g_kh4   [(size_t)BB*HH*TT*DD/8];     // k half [B,H,T,D] (post-rope)
__device__ uint4 g_vh4   [(size_t)BB*HH*DD*TT/8];     // v half [B,H,D,T] (transposed)
__device__ uint4 g_ph4   [(size_t)BH*TT*TT/8];        // probs half
__device__ uint4 g_yh4   [(size_t)BB*TT*CC/8];        // y half [B*T, C]
__device__ float g_q[(size_t)BB*HH*TT*DD];            // raw fp32 q (pre-rope)
__device__ float g_k[(size_t)BB*HH*TT*DD];            // raw fp32 k (pre-rope)
__device__ float g_s[(size_t)BH*TT*TT];               // scores fp32

// ---------------- helpers ----------------
__device__ __forceinline__ void cpa16(uint32_t dst, const void* src) {
    asm volatile("cp.async.cg.shared.global [%0], [%1], 16;" :: "r"(dst), "l"(src));
}

__device__ __forceinline__ void ldsm4(uint32_t* r, uint32_t addr) {
    asm volatile("ldmatrix.sync.aligned.m8n8.x4.shared.b16 {%0,%1,%2,%3}, [%4];"
                 : "=r"(r[0]), "=r"(r[1]), "=r"(r[2]), "=r"(r[3]) : "r"(addr));
}

__device__ __forceinline__ void mma_h(float* d, const uint32_t* a, const uint32_t* b) {
    asm volatile(
        "mma.sync.aligned.m16n8k16.row.col.f32.f16.f16.f32 "
        "{%0,%1,%2,%3}, {%4,%5,%6,%7}, {%8,%9}, {%0,%1,%2,%3};"
        : "+f"(d[0]), "+f"(d[1]), "+f"(d[2]), "+f"(d[3])
        : "r"(a[0]), "r"(a[1]), "r"(a[2]), "r"(a[3]),
          "r"(b[0]), "r"(b[1]));
}

// ---------------- fp16 tensor-core GEMM -----------------------------------
// C = alpha * A * B^T.  A: (M x K) half row-major lda; B: (N x K) half row-major.
// Block 128x128, K-tile 32 halves (64B/row), 128 threads, 4 warps (2M x 2N),
// warp tile 64x64 (acc 4x8x4). Smem: swizzled 64B rows, chunk ^= (row & 3);
// 3 stages, 16KB/stage = 48KB static. One __syncthreads per K-tile.
// EPI 0: fp32 C + z*cOut, *alpha
// EPI 1: qkv scatter -> g_q/g_k fp32 [B,H,T,D], v half transposed [B,H,D,T]
// EPI 2: y half at (b*T+row)*C + h*128 + col   (z = b*HH + h)
#define STG_BYTES 16384u
template<int EPI>
__global__ __launch_bounds__(128)
void hgemm(const __half* __restrict__ A, const __half* __restrict__ B,
           float* __restrict__ C,
           int K, int lda, int ldb, int ldc,
           long batchA, long batchB, long cOut, float alpha)
{
    __shared__ __align__(128) char smem[3 * STG_BYTES];   // 48KB

    const int tid  = threadIdx.x;
    const int lane = tid & 31;
    const int warp = tid >> 5;                // 0..3
    const int warp_m = (warp & 1) * 64;       // 0,64
    const int warp_n = (warp >> 1) * 64;      // 0,64
    const int lg = lane >> 2;
    const int lk = lane & 3;

    const int z = blockIdx.z;
    const __half* Ab = A + (long)z * batchA;
    const __half* Bb = B + (long)z * batchB;
    const int bn = blockIdx.x * 128;
    const int bm = blockIdx.y * 128;

    float acc[4][8][4];
    #pragma unroll
    for (int i = 0; i < 4; i++)
        #pragma unroll
        for (int j = 0; j < 8; j++)
            #pragma unroll
            for (int c = 0; c < 4; c++) acc[i][j][c] = 0.f;

    const uint32_t s0 = (uint32_t)__cvta_generic_to_shared(smem);
    const int nt = K >> 5;

    // ---- cp.async tile loader: A at stage base, B at +8KB ----
    const int strow = tid >> 2;      // 0..31
    const int stc   = tid & 3;
    auto ldtile = [&](int t, int st) {
        uint32_t base = s0 + (uint32_t)st * STG_BYTES;
        int k0 = t << 5;
        #pragma unroll
        for (int p = 0; p < 4; p++) {
            int row = strow + p * 32;
            uint32_t sw = (uint32_t)(row * 64 + ((stc ^ (row & 3)) << 4));
            cpa16(base + sw,         Ab + (long)(bm + row) * lda + k0 + stc * 8);
            cpa16(base + 8192u + sw, Bb + (long)(bn + row) * ldb + k0 + stc * 8);
        }
        asm volatile("cp.async.commit_group;" ::: "memory");
    };

    // ---- ldmatrix per-lane rows ----
    const int rowA  = warp_m + (lane & 15);
    const int chA   = lane >> 4;
    const int rowB  = warp_n + (lane & 7) + ((lane >> 4) << 3);
    const int chB   = (lane >> 3) & 1;

    ldtile(0, 0);
    if (nt > 1) ldtile(1, 1);

    for (int it = 0; it < nt; it++) {
        if (it + 1 < nt) asm volatile("cp.async.wait_group 1;" ::: "memory");
        else             asm volatile("cp.async.wait_group 0;" ::: "memory");
        __syncthreads();   // orders prior-iter LDSMs before stage reuse below

        if (it + 2 < nt) ldtile(it + 2, (it + 2) % 3);

        uint32_t abase = s0 + (uint32_t)(it % 3) * STG_BYTES;
        uint32_t bbase = abase + 8192u;

        #pragma unroll
        for (int ks = 0; ks < 2; ks++) {
            int kc = ks * 2;
            uint32_t af[4][4];
            #pragma unroll
            for (int i = 0; i < 4; i++) {
                int r = rowA + i * 16;
                ldsm4(af[i], abase + r * 64 + (((kc + chA) ^ (r & 3)) << 4));
            }
            uint32_t bf[8][2];
            #pragma unroll
            for (int j4 = 0; j4 < 4; j4++) {
                int r = rowB + j4 * 16;
                uint32_t t4[4];
                ldsm4(t4, bbase + r * 64 + (((kc + chB) ^ (r & 3)) << 4));
                bf[j4 * 2][0]     = t4[0];
                bf[j4 * 2][1]     = t4[1];
                bf[j4 * 2 + 1][0] = t4[2];
                bf[j4 * 2 + 1][1] = t4[3];
            }
            #pragma unroll
            for (int i = 0; i < 4; i++)
                #pragma unroll
                for (int j = 0; j < 8; j++)
                    mma_h(acc[i][j], af[i], bf[j]);
        }
    }

    // ---- epilogue ----
    if (EPI == 0) {
        float* Cb = C + (long)z * cOut;
        #pragma unroll
        for (int i = 0; i < 4; i++) {
            long r0 = bm + warp_m + i * 16 + lg;
            #pragma unroll
            for (int j = 0; j < 8; j++) {
                int col = bn + warp_n + j * 8 + lk * 2;
                *(float2*)&Cb[r0 * ldc + col] =
                    make_float2(alpha * acc[i][j][0], alpha * acc[i][j][1]);
                *(float2*)&Cb[(r0 + 8) * ldc + col] =
                    make_float2(alpha * acc[i][j][2], alpha * acc[i][j][3]);
            }
        }
    } else if (EPI == 1) {
        int sel = bn >> 11;
        int h   = (bn & 2047) >> 7;
        #pragma unroll
        for (int i = 0; i < 4; i++) {
            int rowm = bm + warp_m + i * 16 + lg;
            int b = rowm >> 11;
            int t = rowm & 2047;
            if (sel < 2) {
                float* dst = sel ? g_k : g_q;
                long base = ((long)(b * HH + h) * TT + t) * DD;
                #pragma unroll
                for (int j = 0; j < 8; j++) {
                    int d = warp_n + j * 8 + lk * 2;
                    *(float2*)&dst[base + d] =
                        make_float2(acc[i][j][0], acc[i][j][1]);
                    *(float2*)&dst[base + 8 * DD + d] =
                        make_float2(acc[i][j][2], acc[i][j][3]);
                }
            } else {
                __half* vh = (__half*)g_vh4;
                long vb = (long)(b * HH + h) * DD * TT;
                #pragma unroll
                for (int j = 0; j < 8; j++) {
                    int d = warp_n + j * 8 + lk * 2;
                    vh[vb + (long)d       * TT + t]     = __float2half_rn(acc[i][j][0]);
                    vh[vb + (long)(d + 1) * TT + t]     = __float2half_rn(acc[i][j][1]);
                    vh[vb + (long)d       * TT + t + 8] = __float2half_rn(acc[i][j][2]);
                    vh[vb + (long)(d + 1) * TT + t + 8] = __float2half_rn(acc[i][j][3]);
                }
            }
        }
    } else { // EPI == 2
        __half* yh = (__half*)g_yh4;
        int h = z % HH, b = z / HH;
        #pragma unroll
        for (int i = 0; i < 4; i++) {
            int rowm = bm + warp_m + i * 16 + lg;
            long base = ((long)(b * TT + rowm)) * CC + h * DD;
            #pragma unroll
            for (int j = 0; j < 8; j++) {
                int col = warp_n + j * 8 + lk * 2;
                *(__half2*)&yh[base + col] =
                    __floats2half2_rn(acc[i][j][0], acc[i][j][1]);
                *(__half2*)&yh[base + 8 * CC + col] =
                    __floats2half2_rn(acc[i][j][2], acc[i][j][3]);
            }
        }
    }
}

// ---------------- prepass: fp32 -> fp16 ----------------
__global__ __launch_bounds__(256)
void f2h_kernel(const float4* __restrict__ src, uint2* __restrict__ dst, int n4)
{
    int i = blockIdx.x * blockDim.x + threadIdx.x;
    if (i >= n4) return;
    float4 v = src[i];
    uint2 o;
    __half2 lo = __floats2half2_rn(v.x, v.y);
    __half2 hi = __floats2half2_rn(v.z, v.w);
    o.x = *(uint32_t*)&lo;
    o.y = *(uint32_t*)&hi;
    dst[i] = o;
}

__global__ __launch_bounds__(256)
void transpose_h_kernel(const float* __restrict__ src, __half* __restrict__ dst,
                        int R, int C)
{
    __shared__ float t[32][33];
    int c0 = blockIdx.x * 32, r0 = blockIdx.y * 32;
    int tx = threadIdx.x, ty = threadIdx.y;   // (32, 8)
    #pragma unroll
    for (int i = 0; i < 32; i += 8)
        t[ty + i][tx] = src[(long)(r0 + ty + i) * C + c0 + tx];
    __syncthreads();
    #pragma unroll
    for (int i = 0; i < 32; i += 8)
        dst[(long)(c0 + ty + i) * R + r0 + tx] = __float2half_rn(t[tx][ty + i]);
}

// ---------------- RoPE: fp32 q/k -> rotated fp16 qh/kh ----------------
__global__ __launch_bounds__(256)
void rope_kernel(const float* __restrict__ cosb, const float* __restrict__ sinb)
{
    long idx = (long)blockIdx.x * blockDim.x + threadIdx.x;
    const long total = (long)BB * HH * TT * 64;
    if (idx >= total) return;
    int d = idx & 63;
    long r = idx >> 6;
    int t = (int)(r % TT);
    long base = r * DD + d;
    float c = cosb[t * DD + d];
    float s = sinb[t * DD + d];
    __half* qh = (__half*)g_qh4;
    __half* kh = (__half*)g_kh4;
    float q0 = g_q[base], q1 = g_q[base + 64];
    qh[base]      = __float2half_rn(q0 * c - q1 * s);
    qh[base + 64] = __float2half_rn(q1 * c + q0 * s);
    float k0 = g_k[base], k1 = g_k[base + 64];
    kh[base]      = __float2half_rn(k0 * c - k1 * s);
    kh[base + 64] = __float2half_rn(k1 * c + k0 * s);
}

// ---------------- row softmax: fp32 scores -> fp16 probs ----------------
__global__ __launch_bounds__(256)
void softmax_kernel()
{
    long row = blockIdx.x;
    const float* p = g_s + row * (long)TT;
    __half* ph = (__half*)g_ph4 + row * (long)TT;
    int tid = threadIdx.x;
    float v[8];
    float mx = -1e30f;
    #pragma unroll
    for (int i = 0; i < 8; i++) {
        v[i] = p[tid + i * 256];
        mx = fmaxf(mx, v[i]);
    }
    __shared__ float sm[8];
    #pragma unroll
    for (int o = 16; o; o >>= 1) mx = fmaxf(mx, __shfl_xor_sync(0xffffffffu, mx, o));
    if ((tid & 31) == 0) sm[tid >> 5] = mx;
    __syncthreads();
    float rowmax = sm[0];
    #pragma unroll
    for (int w = 1; w < 8; w++) rowmax = fmaxf(rowmax, sm[w]);
    __syncthreads();

    float sum = 0.f;
    #pragma unroll
    for (int i = 0; i < 8; i++) {
        v[i] = expf(v[i] - rowmax);
        sum += v[i];
    }
    #pragma unroll
    for (int o = 16; o; o >>= 1) sum += __shfl_xor_sync(0xffffffffu, sum, o);
    if ((tid & 31) == 0) sm[tid >> 5] = sum;
    __syncthreads();
    float rowsum = 0.f;
    #pragma unroll
    for (int w = 0; w < 8; w++) rowsum += sm[w];
    float inv = 1.f / rowsum;
    #pragma unroll
    for (int i = 0; i < 8; i++) ph[tid + i * 256] = __float2half_rn(v[i] * inv);
}

// ---------------- launch ----------------
extern "C" void kernel_launch(void* const* d_in, const int* in_sizes, int n_in,
                              void* d_out, int out_size)
{
    const float* x     = (const float*)d_in[0];
    const float* cosb  = (const float*)d_in[1];
    const float* sinb  = (const float*)d_in[2];
    const float* Wqkv  = (const float*)d_in[3];
    const float* Wproj = (const float*)d_in[4];
    float* out = (float*)d_out;

    void *xh, *wqkvT, *wprojT, *qh, *kh, *vh, *ph, *yh;
    float *s;
    cudaGetSymbolAddress(&xh,     g_xh4);
    cudaGetSymbolAddress(&wqkvT,  g_wqkvT4);
    cudaGetSymbolAddress(&wprojT, g_wprojT4);
    cudaGetSymbolAddress(&qh, g_qh4);
    cudaGetSymbolAddress(&kh, g_kh4);
    cudaGetSymbolAddress(&vh, g_vh4);
    cudaGetSymbolAddress(&ph, g_ph4);
    cudaGetSymbolAddress(&yh, g_yh4);
    cudaGetSymbolAddress((void**)&s, g_s);

    const float scale = 0.08838834764831845f;  // 1/sqrt(128)

    // 0) prepass: x -> half; W_qkv^T, W_proj^T -> half
    {
        int n4 = (BB * TT * CC) / 4;
        f2h_kernel<<<(n4 + 255) / 256, 256>>>((const float4*)x, (uint2*)xh, n4);
        transpose_h_kernel<<<dim3(3 * CC / 32, CC / 32), dim3(32, 8)>>>(Wqkv,  (__half*)wqkvT,  CC, 3 * CC);
        transpose_h_kernel<<<dim3(CC / 32,     CC / 32), dim3(32, 8)>>>(Wproj, (__half*)wprojT, CC, CC);
    }

    // 1) qkv = x @ W_qkv  -> q,k fp32 [B,H,T,D]; v half [B,H,D,T]
    hgemm<1><<<dim3(48, 32, 1), 128>>>(
        (const __half*)xh, (const __half*)wqkvT, nullptr,
        2048, 2048, 2048, 0,
        0L, 0L, 0L, 1.0f);

    // 2) RoPE -> qh, kh (half)
    rope_kernel<<<16384, 256>>>(cosb, sinb);

    // 3) scores = scale * Q @ K^T -> g_s fp32 (batched over B*H)
    hgemm<0><<<dim3(16, 16, BH), 128>>>(
        (const __half*)qh, (const __half*)kh, s,
        128, 128, 128, 2048,
        (long)TT * DD, (long)TT * DD, (long)TT * TT, scale);

    // 4) softmax -> probs half
    softmax_kernel<<<BH * TT, 256>>>();

    // 5) y = P @ V -> yh half [B*T, C]
    hgemm<2><<<dim3(1, 16, BH), 128>>>(
        (const __half*)ph, (const __half*)vh, nullptr,
        2048, 2048, 2048, 0,
        (long)TT * TT, (long)DD * TT, 0L, 1.0f);

    // 6) out = y @ W_proj -> fp32
    hgemm<0><<<dim3(16, 32, 1), 128>>>(
        (const __half*)yh, (const __half*)wprojT, out,
        2048, 2048, 2048, 2048,
        0L, 0L, 0L, 1.0f);
}